// round 1
// baseline (speedup 1.0000x reference)
#include <cuda_runtime.h>
#include <cstdint>
#include <cstddef>

// Problem dims (fixed)
#define DIM_  2048
#define CTX_  4096
#define LQ_   8192
#define SK_   512
#define NH_   16
#define HD_   128

// Scratch (device globals: allocation-free per harness rules)
__device__ float g_Q[(size_t)LQ_ * DIM_];   // 64 MB
__device__ float g_K[(size_t)SK_ * DIM_];   //  4 MB
__device__ float g_V[(size_t)SK_ * DIM_];   //  4 MB
__device__ float g_A[(size_t)LQ_ * DIM_];   // 64 MB

// ---------------------------------------------------------------------------
// helpers
// ---------------------------------------------------------------------------
__device__ __forceinline__ unsigned f2tf(float x) {
    unsigned r;
    asm("cvt.rna.tf32.f32 %0, %1;" : "=r"(r) : "f"(x));
    return r;
}

__device__ __forceinline__ void mma8(float* c, const unsigned* a, unsigned b0, unsigned b1) {
    asm volatile(
        "mma.sync.aligned.m16n8k8.row.col.f32.tf32.tf32.f32 "
        "{%0,%1,%2,%3},{%4,%5,%6,%7},{%8,%9},{%0,%1,%2,%3};"
        : "+f"(c[0]), "+f"(c[1]), "+f"(c[2]), "+f"(c[3])
        : "r"(a[0]), "r"(a[1]), "r"(a[2]), "r"(a[3]), "r"(b0), "r"(b1));
}

// ---------------------------------------------------------------------------
// GEMM: C[M,N] = A[M,K] @ B[K,N] + bias[N]    (all row-major fp32, TF32 mma)
// CTA tile 128x128, K tile 16, 256 threads = 8 warps (4x2), warp tile 32x64.
// ---------------------------------------------------------------------------
#define BM 128
#define BN 128
#define BK 16

__global__ void __launch_bounds__(256)
gemm_bias_tf32(const float* __restrict__ A, const float* __restrict__ B,
               const float* __restrict__ bias, float* __restrict__ C,
               int M, int N, int K)
{
    __shared__ unsigned As[2][BK][BM + 4];   // transposed: As[k][m]
    __shared__ unsigned Bs[2][BK][BN + 4];   // Bs[k][n]

    const int tid  = threadIdx.x;
    const int wid  = tid >> 5;
    const int lane = tid & 31;
    const int g    = lane >> 2;   // 0..7
    const int c    = lane & 3;    // 0..3
    const int wm   = (wid >> 1) * 32;   // warp row offset (0,32,64,96)
    const int wn   = (wid & 1) * 64;    // warp col offset (0,64)
    const int m0   = blockIdx.y * BM;
    const int n0   = blockIdx.x * BN;

    float acc[2][8][4];
#pragma unroll
    for (int i = 0; i < 2; i++)
#pragma unroll
        for (int j = 0; j < 8; j++)
#pragma unroll
            for (int t = 0; t < 4; t++) acc[i][j][t] = 0.f;

    const int nkt = K / BK;

    // ---- tile loaders ----
    auto load_tiles = [&](int buf, int kt) {
        const int k0 = kt * BK;
        // A tile: 128 rows x 16 cols = 512 float4
#pragma unroll
        for (int i = 0; i < 2; i++) {
            int v   = tid + i * 256;
            int row = v >> 2;
            int kv  = (v & 3) * 4;
            const float4 x = *reinterpret_cast<const float4*>(
                &A[(size_t)(m0 + row) * K + k0 + kv]);
            As[buf][kv + 0][row] = f2tf(x.x);
            As[buf][kv + 1][row] = f2tf(x.y);
            As[buf][kv + 2][row] = f2tf(x.z);
            As[buf][kv + 3][row] = f2tf(x.w);
        }
        // B tile: 16 rows x 128 cols = 512 float4
#pragma unroll
        for (int i = 0; i < 2; i++) {
            int v   = tid + i * 256;
            int row = v >> 5;
            int nv  = (v & 31) * 4;
            const float4 x = *reinterpret_cast<const float4*>(
                &B[(size_t)(k0 + row) * N + n0 + nv]);
            Bs[buf][row][nv + 0] = f2tf(x.x);
            Bs[buf][row][nv + 1] = f2tf(x.y);
            Bs[buf][row][nv + 2] = f2tf(x.z);
            Bs[buf][row][nv + 3] = f2tf(x.w);
        }
    };

    load_tiles(0, 0);
    __syncthreads();

    for (int kt = 0; kt < nkt; kt++) {
        const int buf = kt & 1;
        if (kt + 1 < nkt) load_tiles(buf ^ 1, kt + 1);

#pragma unroll
        for (int ks = 0; ks < 2; ks++) {
            const int k8 = ks * 8;
            unsigned a[2][4], b[8][2];
#pragma unroll
            for (int mt = 0; mt < 2; mt++) {
                int r = wm + mt * 16 + g;
                a[mt][0] = As[buf][k8 + c][r];
                a[mt][1] = As[buf][k8 + c][r + 8];
                a[mt][2] = As[buf][k8 + c + 4][r];
                a[mt][3] = As[buf][k8 + c + 4][r + 8];
            }
#pragma unroll
            for (int nt = 0; nt < 8; nt++) {
                int n = wn + nt * 8 + g;
                b[nt][0] = Bs[buf][k8 + c][n];
                b[nt][1] = Bs[buf][k8 + c + 4][n];
            }
#pragma unroll
            for (int mt = 0; mt < 2; mt++)
#pragma unroll
                for (int nt = 0; nt < 8; nt++)
                    mma8(acc[mt][nt], a[mt], b[nt][0], b[nt][1]);
        }
        __syncthreads();
    }

    // ---- epilogue: bias + store ----
#pragma unroll
    for (int mt = 0; mt < 2; mt++) {
        int row = m0 + wm + mt * 16 + g;
#pragma unroll
        for (int nt = 0; nt < 8; nt++) {
            int col = n0 + wn + nt * 8 + 2 * c;
            float b0 = bias[col], b1 = bias[col + 1];
            C[(size_t)row * N + col]           = acc[mt][nt][0] + b0;
            C[(size_t)row * N + col + 1]       = acc[mt][nt][1] + b1;
            C[(size_t)(row + 8) * N + col]     = acc[mt][nt][2] + b0;
            C[(size_t)(row + 8) * N + col + 1] = acc[mt][nt][3] + b1;
        }
    }
}

// ---------------------------------------------------------------------------
// RMSNorm over rows of length DIM_ (in place), with learned weight.
// One CTA (256 threads) per row.
// ---------------------------------------------------------------------------
__global__ void __launch_bounds__(256)
rmsnorm_rows(float* __restrict__ X, const float* __restrict__ gw)
{
    const int N = DIM_;
    float* x = X + (size_t)blockIdx.x * N;

    float ss = 0.f;
    for (int i = threadIdx.x; i < N / 4; i += 256) {
        float4 v = reinterpret_cast<float4*>(x)[i];
        ss += v.x * v.x + v.y * v.y + v.z * v.z + v.w * v.w;
    }
#pragma unroll
    for (int off = 16; off; off >>= 1) ss += __shfl_xor_sync(0xFFFFFFFFu, ss, off);

    __shared__ float red[8];
    if ((threadIdx.x & 31) == 0) red[threadIdx.x >> 5] = ss;
    __syncthreads();
    float tot = 0.f;
#pragma unroll
    for (int i = 0; i < 8; i++) tot += red[i];

    const float sc = rsqrtf(tot / (float)N + 1e-6f);

    for (int i = threadIdx.x; i < N / 4; i += 256) {
        float4 v = reinterpret_cast<float4*>(x)[i];
        float4 w = reinterpret_cast<const float4*>(gw)[i];
        v.x *= sc * w.x; v.y *= sc * w.y; v.z *= sc * w.z; v.w *= sc * w.w;
        reinterpret_cast<float4*>(x)[i] = v;
    }
}

// ---------------------------------------------------------------------------
// Attention: per CTA = one head x 32 query rows. Full S=512 scores in smem.
// Two passes: QK^T (TF32 mma) -> softmax (fp32) -> P@V (TF32 mma).
// 256 threads = 8 warps.
// ---------------------------------------------------------------------------
#define ATTN_SMEM ((32 * 132 + 64 * 132 + 32 * 516 + 32) * 4)

__global__ void __launch_bounds__(256)
attn_kernel(const float* __restrict__ Q, const float* __restrict__ Kc,
            const float* __restrict__ V, float* __restrict__ O)
{
    extern __shared__ float sm[];
    unsigned* Qs  = reinterpret_cast<unsigned*>(sm);          // [32][132] tf32
    unsigned* KVs = Qs + 32 * 132;                            // [64][132] tf32
    float*    Sc  = reinterpret_cast<float*>(KVs + 64 * 132); // [32][516]
    float*    rsum = Sc + 32 * 516;                           // [32]

    const int tid  = threadIdx.x;
    const int wid  = tid >> 5;
    const int lane = tid & 31;
    const int g    = lane >> 2;
    const int c    = lane & 3;
    const int l0   = blockIdx.x * 32;
    const int h    = blockIdx.y;
    const float scale = 0.08838834764831845f;   // 1/sqrt(128)

    // load Q tile (scaled, tf32-converted): 32 rows x 128 = 1024 float4
#pragma unroll
    for (int i = 0; i < 4; i++) {
        int v   = tid + i * 256;
        int row = v >> 5;
        int dv  = (v & 31) * 4;
        const float4 q = *reinterpret_cast<const float4*>(
            &Q[(size_t)(l0 + row) * DIM_ + h * HD_ + dv]);
        Qs[row * 132 + dv + 0] = f2tf(q.x * scale);
        Qs[row * 132 + dv + 1] = f2tf(q.y * scale);
        Qs[row * 132 + dv + 2] = f2tf(q.z * scale);
        Qs[row * 132 + dv + 3] = f2tf(q.w * scale);
    }

    // ---- pass 1: scores = (Q*scale) @ K^T ----
    for (int t = 0; t < 8; t++) {
        const int s0 = t * 64;
        __syncthreads();   // previous KVs consumers done (also covers Qs writes at t=0)
#pragma unroll
        for (int i = 0; i < 8; i++) {
            int v   = tid + i * 256;
            int row = v >> 5;                  // 0..63
            int dv  = (v & 31) * 4;
            const float4 kv = *reinterpret_cast<const float4*>(
                &Kc[(size_t)(s0 + row) * DIM_ + h * HD_ + dv]);
            KVs[row * 132 + dv + 0] = f2tf(kv.x);
            KVs[row * 132 + dv + 1] = f2tf(kv.y);
            KVs[row * 132 + dv + 2] = f2tf(kv.z);
            KVs[row * 132 + dv + 3] = f2tf(kv.w);
        }
        __syncthreads();

        // warp `wid` computes score cols [s0 + wid*8, +8) for all 32 rows
        float acc[2][4];
#pragma unroll
        for (int mt = 0; mt < 2; mt++)
#pragma unroll
            for (int i = 0; i < 4; i++) acc[mt][i] = 0.f;

#pragma unroll
        for (int ks = 0; ks < 16; ks++) {
            const int k8 = ks * 8;
            unsigned a[2][4];
#pragma unroll
            for (int mt = 0; mt < 2; mt++) {
                int r = mt * 16 + g;
                a[mt][0] = Qs[r * 132 + k8 + c];
                a[mt][1] = Qs[(r + 8) * 132 + k8 + c];
                a[mt][2] = Qs[r * 132 + k8 + c + 4];
                a[mt][3] = Qs[(r + 8) * 132 + k8 + c + 4];
            }
            unsigned b0 = KVs[(wid * 8 + g) * 132 + k8 + c];
            unsigned b1 = KVs[(wid * 8 + g) * 132 + k8 + c + 4];
#pragma unroll
            for (int mt = 0; mt < 2; mt++) mma8(acc[mt], a[mt], b0, b1);
        }
#pragma unroll
        for (int mt = 0; mt < 2; mt++) {
            int r   = mt * 16 + g;
            int col = s0 + wid * 8 + 2 * c;
            Sc[r * 516 + col]           = acc[mt][0];
            Sc[r * 516 + col + 1]       = acc[mt][1];
            Sc[(r + 8) * 516 + col]     = acc[mt][2];
            Sc[(r + 8) * 516 + col + 1] = acc[mt][3];
        }
    }
    __syncthreads();

    // ---- softmax over 512 cols: warp wid handles rows 4*wid .. 4*wid+3 ----
#pragma unroll
    for (int rr = 0; rr < 4; rr++) {
        const int row = wid * 4 + rr;
        float mx = -1e30f;
        for (int j = lane; j < 512; j += 32) mx = fmaxf(mx, Sc[row * 516 + j]);
#pragma unroll
        for (int off = 16; off; off >>= 1)
            mx = fmaxf(mx, __shfl_xor_sync(0xFFFFFFFFu, mx, off));
        float sum = 0.f;
        for (int j = lane; j < 512; j += 32) {
            float e = __expf(Sc[row * 516 + j] - mx);
            sum += e;
            Sc[row * 516 + j] = __uint_as_float(f2tf(e));  // store tf32 bits for mma A
        }
#pragma unroll
        for (int off = 16; off; off >>= 1) sum += __shfl_xor_sync(0xFFFFFFFFu, sum, off);
        if (lane == 0) rsum[row] = sum;
    }

    // ---- pass 2: O = P @ V ----
    float o[2][2][4];
#pragma unroll
    for (int mt = 0; mt < 2; mt++)
#pragma unroll
        for (int nt = 0; nt < 2; nt++)
#pragma unroll
            for (int i = 0; i < 4; i++) o[mt][nt][i] = 0.f;

    for (int t = 0; t < 8; t++) {
        const int s0 = t * 64;
        __syncthreads();   // covers softmax writes (t=0) and KVs reuse (t>0)
#pragma unroll
        for (int i = 0; i < 8; i++) {
            int v   = tid + i * 256;
            int row = v >> 5;
            int dv  = (v & 31) * 4;
            const float4 vv = *reinterpret_cast<const float4*>(
                &V[(size_t)(s0 + row) * DIM_ + h * HD_ + dv]);
            KVs[row * 132 + dv + 0] = f2tf(vv.x);
            KVs[row * 132 + dv + 1] = f2tf(vv.y);
            KVs[row * 132 + dv + 2] = f2tf(vv.z);
            KVs[row * 132 + dv + 3] = f2tf(vv.w);
        }
        __syncthreads();

        // warp wid computes O cols [wid*16, +16)
#pragma unroll
        for (int ks = 0; ks < 8; ks++) {
            const int kk = s0 + ks * 8;
            unsigned a[2][4];
#pragma unroll
            for (int mt = 0; mt < 2; mt++) {
                int r = mt * 16 + g;
                a[mt][0] = __float_as_uint(Sc[r * 516 + kk + c]);
                a[mt][1] = __float_as_uint(Sc[(r + 8) * 516 + kk + c]);
                a[mt][2] = __float_as_uint(Sc[r * 516 + kk + c + 4]);
                a[mt][3] = __float_as_uint(Sc[(r + 8) * 516 + kk + c + 4]);
            }
#pragma unroll
            for (int nt = 0; nt < 2; nt++) {
                int n = wid * 16 + nt * 8 + g;
                unsigned b0 = KVs[(ks * 8 + c) * 132 + n];
                unsigned b1 = KVs[(ks * 8 + c + 4) * 132 + n];
#pragma unroll
                for (int mt = 0; mt < 2; mt++) mma8(o[mt][nt], a[mt], b0, b1);
            }
        }
    }

    // ---- epilogue: divide by row sums, write out ----
#pragma unroll
    for (int mt = 0; mt < 2; mt++) {
        const float inv0 = 1.f / rsum[mt * 16 + g];
        const float inv1 = 1.f / rsum[mt * 16 + g + 8];
        const int row = l0 + mt * 16 + g;
#pragma unroll
        for (int nt = 0; nt < 2; nt++) {
            int col = h * HD_ + wid * 16 + nt * 8 + 2 * c;
            O[(size_t)row * DIM_ + col]           = o[mt][nt][0] * inv0;
            O[(size_t)row * DIM_ + col + 1]       = o[mt][nt][1] * inv0;
            O[(size_t)(row + 8) * DIM_ + col]     = o[mt][nt][2] * inv1;
            O[(size_t)(row + 8) * DIM_ + col + 1] = o[mt][nt][3] * inv1;
        }
    }
}

// ---------------------------------------------------------------------------
// kernel_launch
// ---------------------------------------------------------------------------
extern "C" void kernel_launch(void* const* d_in, const int* in_sizes, int n_in,
                              void* d_out, int out_size)
{
    const float* x   = (const float*)d_in[0];
    const float* ctx = (const float*)d_in[1];
    const float* Wq  = (const float*)d_in[2];
    const float* bq  = (const float*)d_in[3];
    const float* Wk  = (const float*)d_in[4];
    const float* bk  = (const float*)d_in[5];
    const float* Wv  = (const float*)d_in[6];
    const float* bv  = (const float*)d_in[7];
    const float* Wo  = (const float*)d_in[8];
    const float* bo  = (const float*)d_in[9];
    const float* gq  = (const float*)d_in[10];
    const float* gk  = (const float*)d_in[11];
    float* out = (float*)d_out;

    float *Qp, *Kp, *Vp, *Ap;
    cudaGetSymbolAddress((void**)&Qp, g_Q);
    cudaGetSymbolAddress((void**)&Kp, g_K);
    cudaGetSymbolAddress((void**)&Vp, g_V);
    cudaGetSymbolAddress((void**)&Ap, g_A);

    cudaFuncSetAttribute(attn_kernel,
                         cudaFuncAttributeMaxDynamicSharedMemorySize, ATTN_SMEM);

    // Q = rmsnorm(x @ Wq + bq)
    gemm_bias_tf32<<<dim3(DIM_ / BN, LQ_ / BM), 256>>>(x, Wq, bq, Qp, LQ_, DIM_, DIM_);
    rmsnorm_rows<<<LQ_, 256>>>(Qp, gq);

    // K = rmsnorm(ctx @ Wk + bk), V = ctx @ Wv + bv
    gemm_bias_tf32<<<dim3(DIM_ / BN, SK_ / BM), 256>>>(ctx, Wk, bk, Kp, SK_, DIM_, CTX_);
    rmsnorm_rows<<<SK_, 256>>>(Kp, gk);
    gemm_bias_tf32<<<dim3(DIM_ / BN, SK_ / BM), 256>>>(ctx, Wv, bv, Vp, SK_, DIM_, CTX_);

    // attention
    attn_kernel<<<dim3(LQ_ / 32, NH_), 256, ATTN_SMEM>>>(Qp, Kp, Vp, Ap);

    // out = A @ Wo + bo
    gemm_bias_tf32<<<dim3(DIM_ / BN, LQ_ / BM), 256>>>(Ap, Wo, bo, out, LQ_, DIM_, DIM_);
}

// round 3
// speedup vs baseline: 1.4483x; 1.4483x over previous
#include <cuda_runtime.h>
#include <cstdint>
#include <cstddef>

// Problem dims (fixed)
#define DIM_  2048
#define CTX_  4096
#define LQ_   8192
#define SK_   512
#define NH_   16
#define HD_   128

// ---------------------------------------------------------------------------
// Scratch (device globals: allocation-free per harness rules)
// ---------------------------------------------------------------------------
__device__ float g_Q  [(size_t)LQ_ * DIM_];          // 64 MB  (Q, normed)
__device__ float g_KV [(size_t)SK_ * (2 * DIM_)];    //  8 MB  (K | V concat, stride 4096)
__device__ float g_A  [(size_t)LQ_ * DIM_];          // 64 MB  (attention out, tf32-rounded)
__device__ float g_xr [(size_t)LQ_ * DIM_];          // 64 MB  (x rounded)
__device__ float g_cr [(size_t)SK_ * CTX_];          //  8 MB  (ctx rounded)
__device__ float g_Wq [(size_t)DIM_ * DIM_];         // 16 MB  (Wq rounded, [K][N])
__device__ float g_Wkv[(size_t)CTX_ * (2 * DIM_)];   // 64 MB  ([K=4096][ Wk cols | Wv cols ])
__device__ float g_Wo [(size_t)DIM_ * DIM_];         // 16 MB
__device__ float g_bkv[2 * DIM_];                    // bk | bv

// ---------------------------------------------------------------------------
// helpers
// ---------------------------------------------------------------------------
__device__ __forceinline__ unsigned f2tf(float x) {
    unsigned r;
    asm("cvt.rna.tf32.f32 %0, %1;" : "=r"(r) : "f"(x));
    return r;
}

__device__ __forceinline__ uint32_t smem_u32(const void* p) {
    uint32_t r;
    asm("{ .reg .u64 t; cvta.to.shared.u64 t, %1; cvt.u32.u64 %0, t; }"
        : "=r"(r) : "l"(p));
    return r;
}

__device__ __forceinline__ void cp16(uint32_t s, const void* g) {
    asm volatile("cp.async.cg.shared.global [%0], [%1], 16;" :: "r"(s), "l"(g));
}

__device__ __forceinline__ void mma8(float* c, const unsigned* a, unsigned b0, unsigned b1) {
    asm volatile(
        "mma.sync.aligned.m16n8k8.row.col.f32.tf32.tf32.f32 "
        "{%0,%1,%2,%3},{%4,%5,%6,%7},{%8,%9},{%0,%1,%2,%3};"
        : "+f"(c[0]), "+f"(c[1]), "+f"(c[2]), "+f"(c[3])
        : "r"(a[0]), "r"(a[1]), "r"(a[2]), "r"(a[3]), "r"(b0), "r"(b1));
}

// ---------------------------------------------------------------------------
// Pre-pass: round fp32 -> tf32(rna)
// ---------------------------------------------------------------------------
__global__ void __launch_bounds__(256)
round_copy(const float* __restrict__ in, float* __restrict__ out, int n4)
{
    int i = blockIdx.x * 256 + threadIdx.x;
    int stride = gridDim.x * 256;
    for (; i < n4; i += stride) {
        float4 v = reinterpret_cast<const float4*>(in)[i];
        v.x = __uint_as_float(f2tf(v.x));
        v.y = __uint_as_float(f2tf(v.y));
        v.z = __uint_as_float(f2tf(v.z));
        v.w = __uint_as_float(f2tf(v.w));
        reinterpret_cast<float4*>(out)[i] = v;
    }
}

// rounded copy with row restride: in[r][0..cols) -> out[r*ostride + 0..cols)
__global__ void __launch_bounds__(256)
round_copy_cols(const float* __restrict__ in, float* __restrict__ out,
                int cols4, int ostride4, int n4)
{
    int i = blockIdx.x * 256 + threadIdx.x;
    int stride = gridDim.x * 256;
    for (; i < n4; i += stride) {
        int r  = i / cols4;
        int c4 = i - r * cols4;
        float4 v = reinterpret_cast<const float4*>(in)[i];
        v.x = __uint_as_float(f2tf(v.x));
        v.y = __uint_as_float(f2tf(v.y));
        v.z = __uint_as_float(f2tf(v.z));
        v.w = __uint_as_float(f2tf(v.w));
        reinterpret_cast<float4*>(out)[(size_t)r * ostride4 + c4] = v;
    }
}

// ---------------------------------------------------------------------------
// TF32 mma.sync GEMM: C[M,Ntot] = A[M,K] @ B[K,Ntot] + bias
// A,B pre-rounded to tf32. CTA tile 128x128, BK=32, 4-stage cp.async.
// 512 threads = 16 warps (4x4), warp tile 32x32.
// Smem: A [128][36] floats (bank-conflict-free frags), B [32][136] floats.
// ---------------------------------------------------------------------------
#define BM 128
#define BN 128
#define BK 32
#define NSTG 4
#define A_BYTES (128 * 36 * 4)          // 18432
#define STG_BYTES (A_BYTES + 32 * 136 * 4)  // 18432 + 17408 = 35840
#define GEMM_SMEM (NSTG * STG_BYTES)    // 143360

__global__ void __launch_bounds__(512, 1)
gemm_tf32(const float* __restrict__ A, const float* __restrict__ B,
          const float* __restrict__ bias, float* __restrict__ C,
          int Ntot, int K)
{
    extern __shared__ char dsm[];
    const uint32_t sbase = smem_u32(dsm);

    const int tid  = threadIdx.x;
    const int wid  = tid >> 5;
    const int lane = tid & 31;
    const int g    = lane >> 2;   // 0..7
    const int c    = lane & 3;    // 0..3
    const int wm   = (wid >> 2) * 32;   // 0,32,64,96
    const int wn   = (wid & 3) * 32;    // 0,32,64,96
    const int m0   = blockIdx.y * BM;
    const int n0   = blockIdx.x * BN;

    const float* Ap = A + (size_t)m0 * K;
    const float* Bp = B + n0;

    // precompute loader offsets (4 cp16 per thread per stage)
    int a_row[2], a_kp[2], b_row[2], b_np[2];
#pragma unroll
    for (int i = 0; i < 2; i++) {
        int v = tid + i * 512;
        a_row[i] = v >> 3;  a_kp[i] = v & 7;     // A: 128 rows x 8 float4
        b_row[i] = v >> 5;  b_np[i] = v & 31;    // B: 32 rows x 32 float4
    }

    auto load_stage = [&](int s) {
        const uint32_t sb = sbase + (uint32_t)(s & 3) * STG_BYTES;
        const size_t ka = (size_t)s * BK;
#pragma unroll
        for (int i = 0; i < 2; i++)
            cp16(sb + a_row[i] * 144 + a_kp[i] * 16,
                 Ap + (size_t)a_row[i] * K + ka + a_kp[i] * 4);
#pragma unroll
        for (int i = 0; i < 2; i++)
            cp16(sb + A_BYTES + b_row[i] * 544 + b_np[i] * 16,
                 Bp + (size_t)(ka + b_row[i]) * Ntot + b_np[i] * 4);
    };

    float acc[2][4][4];
#pragma unroll
    for (int mt = 0; mt < 2; mt++)
#pragma unroll
        for (int nt = 0; nt < 4; nt++)
#pragma unroll
            for (int t = 0; t < 4; t++) acc[mt][nt][t] = 0.f;

    const int KT = K / BK;

    // prologue: stages 0..2
#pragma unroll
    for (int s = 0; s < NSTG - 1; s++) {
        load_stage(s);
        asm volatile("cp.async.commit_group;" ::: "memory");
    }

    for (int kt = 0; kt < KT; kt++) {
        if (kt + NSTG - 1 < KT) load_stage(kt + NSTG - 1);
        asm volatile("cp.async.commit_group;" ::: "memory");
        asm volatile("cp.async.wait_group %0;" :: "n"(NSTG - 1) : "memory");
        __syncthreads();

        const unsigned* As = reinterpret_cast<const unsigned*>(
            dsm + (size_t)(kt & 3) * STG_BYTES);
        const unsigned* Bs = reinterpret_cast<const unsigned*>(
            dsm + (size_t)(kt & 3) * STG_BYTES + A_BYTES);

#pragma unroll
        for (int k8 = 0; k8 < BK; k8 += 8) {
            unsigned a[2][4];
#pragma unroll
            for (int mt = 0; mt < 2; mt++) {
                const int r = wm + mt * 16 + g;
                a[mt][0] = As[r * 36 + k8 + c];
                a[mt][1] = As[(r + 8) * 36 + k8 + c];
                a[mt][2] = As[r * 36 + k8 + c + 4];
                a[mt][3] = As[(r + 8) * 36 + k8 + c + 4];
            }
            unsigned b[4][2];
#pragma unroll
            for (int nt = 0; nt < 4; nt++) {
                const int n = wn + nt * 8 + g;
                b[nt][0] = Bs[(k8 + c) * 136 + n];
                b[nt][1] = Bs[(k8 + c + 4) * 136 + n];
            }
#pragma unroll
            for (int mt = 0; mt < 2; mt++)
#pragma unroll
                for (int nt = 0; nt < 4; nt++)
                    mma8(acc[mt][nt], a[mt], b[nt][0], b[nt][1]);
        }
        __syncthreads();
    }

    // epilogue: bias + store
#pragma unroll
    for (int mt = 0; mt < 2; mt++) {
        const int r0 = m0 + wm + mt * 16 + g;
#pragma unroll
        for (int nt = 0; nt < 4; nt++) {
            const int col = n0 + wn + nt * 8 + 2 * c;
            const float2 bb = *reinterpret_cast<const float2*>(bias + col);
            float2 o0, o1;
            o0.x = acc[mt][nt][0] + bb.x;  o0.y = acc[mt][nt][1] + bb.y;
            o1.x = acc[mt][nt][2] + bb.x;  o1.y = acc[mt][nt][3] + bb.y;
            *reinterpret_cast<float2*>(C + (size_t)r0 * Ntot + col)       = o0;
            *reinterpret_cast<float2*>(C + (size_t)(r0 + 8) * Ntot + col) = o1;
        }
    }
}

// ---------------------------------------------------------------------------
// RMSNorm over rows of length DIM_ (in place, arbitrary row stride)
// ---------------------------------------------------------------------------
__global__ void __launch_bounds__(256)
rmsnorm_rows(float* __restrict__ X, const float* __restrict__ gw, int stride)
{
    const int N = DIM_;
    float* x = X + (size_t)blockIdx.x * stride;

    float ss = 0.f;
    for (int i = threadIdx.x; i < N / 4; i += 256) {
        float4 v = reinterpret_cast<float4*>(x)[i];
        ss += v.x * v.x + v.y * v.y + v.z * v.z + v.w * v.w;
    }
#pragma unroll
    for (int off = 16; off; off >>= 1) ss += __shfl_xor_sync(0xFFFFFFFFu, ss, off);

    __shared__ float red[8];
    if ((threadIdx.x & 31) == 0) red[threadIdx.x >> 5] = ss;
    __syncthreads();
    float tot = 0.f;
#pragma unroll
    for (int i = 0; i < 8; i++) tot += red[i];

    const float sc = rsqrtf(tot / (float)N + 1e-6f);

    for (int i = threadIdx.x; i < N / 4; i += 256) {
        float4 v = reinterpret_cast<float4*>(x)[i];
        float4 w = reinterpret_cast<const float4*>(gw)[i];
        v.x *= sc * w.x; v.y *= sc * w.y; v.z *= sc * w.z; v.w *= sc * w.w;
        reinterpret_cast<float4*>(x)[i] = v;
    }
}

// ---------------------------------------------------------------------------
// Attention: per CTA = one head x 32 query rows. Full S=512 scores in smem.
// Two passes: QK^T (TF32 mma) -> softmax (fp32) -> P@V (TF32 mma).
// ---------------------------------------------------------------------------
#define ATTN_SMEM ((32 * 132 + 64 * 132 + 32 * 516 + 32) * 4)

__global__ void __launch_bounds__(256)
attn_kernel(const float* __restrict__ Q, const float* __restrict__ Kc,
            const float* __restrict__ V, float* __restrict__ O, int kvstride)
{
    extern __shared__ float sm[];
    unsigned* Qs  = reinterpret_cast<unsigned*>(sm);          // [32][132]
    unsigned* KVs = Qs + 32 * 132;                            // [64][132]
    float*    Sc  = reinterpret_cast<float*>(KVs + 64 * 132); // [32][516]
    float*    rsum = Sc + 32 * 516;                           // [32]

    const int tid  = threadIdx.x;
    const int wid  = tid >> 5;
    const int lane = tid & 31;
    const int g    = lane >> 2;
    const int c    = lane & 3;
    const int l0   = blockIdx.x * 32;
    const int h    = blockIdx.y;
    const float scale = 0.08838834764831845f;   // 1/sqrt(128)

#pragma unroll
    for (int i = 0; i < 4; i++) {
        int v   = tid + i * 256;
        int row = v >> 5;
        int dv  = (v & 31) * 4;
        const float4 q = *reinterpret_cast<const float4*>(
            &Q[(size_t)(l0 + row) * DIM_ + h * HD_ + dv]);
        Qs[row * 132 + dv + 0] = f2tf(q.x * scale);
        Qs[row * 132 + dv + 1] = f2tf(q.y * scale);
        Qs[row * 132 + dv + 2] = f2tf(q.z * scale);
        Qs[row * 132 + dv + 3] = f2tf(q.w * scale);
    }

    // ---- pass 1: scores ----
    for (int t = 0; t < 8; t++) {
        const int s0 = t * 64;
        __syncthreads();
#pragma unroll
        for (int i = 0; i < 8; i++) {
            int v   = tid + i * 256;
            int row = v >> 5;
            int dv  = (v & 31) * 4;
            const float4 kv = *reinterpret_cast<const float4*>(
                &Kc[(size_t)(s0 + row) * kvstride + h * HD_ + dv]);
            KVs[row * 132 + dv + 0] = f2tf(kv.x);
            KVs[row * 132 + dv + 1] = f2tf(kv.y);
            KVs[row * 132 + dv + 2] = f2tf(kv.z);
            KVs[row * 132 + dv + 3] = f2tf(kv.w);
        }
        __syncthreads();

        float acc[2][4];
#pragma unroll
        for (int mt = 0; mt < 2; mt++)
#pragma unroll
            for (int i = 0; i < 4; i++) acc[mt][i] = 0.f;

#pragma unroll
        for (int ks = 0; ks < 16; ks++) {
            const int k8 = ks * 8;
            unsigned a[2][4];
#pragma unroll
            for (int mt = 0; mt < 2; mt++) {
                int r = mt * 16 + g;
                a[mt][0] = Qs[r * 132 + k8 + c];
                a[mt][1] = Qs[(r + 8) * 132 + k8 + c];
                a[mt][2] = Qs[r * 132 + k8 + c + 4];
                a[mt][3] = Qs[(r + 8) * 132 + k8 + c + 4];
            }
            unsigned b0 = KVs[(wid * 8 + g) * 132 + k8 + c];
            unsigned b1 = KVs[(wid * 8 + g) * 132 + k8 + c + 4];
#pragma unroll
            for (int mt = 0; mt < 2; mt++) mma8(acc[mt], a[mt], b0, b1);
        }
#pragma unroll
        for (int mt = 0; mt < 2; mt++) {
            int r   = mt * 16 + g;
            int col = s0 + wid * 8 + 2 * c;
            Sc[r * 516 + col]           = acc[mt][0];
            Sc[r * 516 + col + 1]       = acc[mt][1];
            Sc[(r + 8) * 516 + col]     = acc[mt][2];
            Sc[(r + 8) * 516 + col + 1] = acc[mt][3];
        }
    }
    __syncthreads();

    // ---- softmax ----
#pragma unroll
    for (int rr = 0; rr < 4; rr++) {
        const int row = wid * 4 + rr;
        float mx = -1e30f;
        for (int j = lane; j < 512; j += 32) mx = fmaxf(mx, Sc[row * 516 + j]);
#pragma unroll
        for (int off = 16; off; off >>= 1)
            mx = fmaxf(mx, __shfl_xor_sync(0xFFFFFFFFu, mx, off));
        float sum = 0.f;
        for (int j = lane; j < 512; j += 32) {
            float e = __expf(Sc[row * 516 + j] - mx);
            sum += e;
            Sc[row * 516 + j] = __uint_as_float(f2tf(e));
        }
#pragma unroll
        for (int off = 16; off; off >>= 1) sum += __shfl_xor_sync(0xFFFFFFFFu, sum, off);
        if (lane == 0) rsum[row] = sum;
    }

    // ---- pass 2: O = P @ V ----
    float o[2][2][4];
#pragma unroll
    for (int mt = 0; mt < 2; mt++)
#pragma unroll
        for (int nt = 0; nt < 2; nt++)
#pragma unroll
            for (int i = 0; i < 4; i++) o[mt][nt][i] = 0.f;

    for (int t = 0; t < 8; t++) {
        const int s0 = t * 64;
        __syncthreads();
#pragma unroll
        for (int i = 0; i < 8; i++) {
            int v   = tid + i * 256;
            int row = v >> 5;
            int dv  = (v & 31) * 4;
            const float4 vv = *reinterpret_cast<const float4*>(
                &V[(size_t)(s0 + row) * kvstride + h * HD_ + dv]);
            KVs[row * 132 + dv + 0] = f2tf(vv.x);
            KVs[row * 132 + dv + 1] = f2tf(vv.y);
            KVs[row * 132 + dv + 2] = f2tf(vv.z);
            KVs[row * 132 + dv + 3] = f2tf(vv.w);
        }
        __syncthreads();

#pragma unroll
        for (int ks = 0; ks < 8; ks++) {
            const int kk = s0 + ks * 8;
            unsigned a[2][4];
#pragma unroll
            for (int mt = 0; mt < 2; mt++) {
                int r = mt * 16 + g;
                a[mt][0] = __float_as_uint(Sc[r * 516 + kk + c]);
                a[mt][1] = __float_as_uint(Sc[(r + 8) * 516 + kk + c]);
                a[mt][2] = __float_as_uint(Sc[r * 516 + kk + c + 4]);
                a[mt][3] = __float_as_uint(Sc[(r + 8) * 516 + kk + c + 4]);
            }
#pragma unroll
            for (int nt = 0; nt < 2; nt++) {
                int n = wid * 16 + nt * 8 + g;
                unsigned b0 = KVs[(ks * 8 + c) * 132 + n];
                unsigned b1 = KVs[(ks * 8 + c + 4) * 132 + n];
#pragma unroll
                for (int mt = 0; mt < 2; mt++) mma8(o[mt][nt], a[mt], b0, b1);
            }
        }
    }

    // ---- epilogue: normalize + tf32-round (so O-proj truncation is exact) ----
#pragma unroll
    for (int mt = 0; mt < 2; mt++) {
        const float inv0 = 1.f / rsum[mt * 16 + g];
        const float inv1 = 1.f / rsum[mt * 16 + g + 8];
        const int row = l0 + mt * 16 + g;
#pragma unroll
        for (int nt = 0; nt < 2; nt++) {
            int col = h * HD_ + wid * 16 + nt * 8 + 2 * c;
            O[(size_t)row * DIM_ + col]           = __uint_as_float(f2tf(o[mt][nt][0] * inv0));
            O[(size_t)row * DIM_ + col + 1]       = __uint_as_float(f2tf(o[mt][nt][1] * inv0));
            O[(size_t)(row + 8) * DIM_ + col]     = __uint_as_float(f2tf(o[mt][nt][2] * inv1));
            O[(size_t)(row + 8) * DIM_ + col + 1] = __uint_as_float(f2tf(o[mt][nt][3] * inv1));
        }
    }
}

// ---------------------------------------------------------------------------
// kernel_launch
// ---------------------------------------------------------------------------
extern "C" void kernel_launch(void* const* d_in, const int* in_sizes, int n_in,
                              void* d_out, int out_size)
{
    const float* x   = (const float*)d_in[0];
    const float* ctx = (const float*)d_in[1];
    const float* Wq  = (const float*)d_in[2];
    const float* bq  = (const float*)d_in[3];
    const float* Wk  = (const float*)d_in[4];
    const float* bk  = (const float*)d_in[5];
    const float* Wv  = (const float*)d_in[6];
    const float* bv  = (const float*)d_in[7];
    const float* Wo  = (const float*)d_in[8];
    const float* bo  = (const float*)d_in[9];
    const float* gq  = (const float*)d_in[10];
    const float* gk  = (const float*)d_in[11];
    float* out = (float*)d_out;

    float *Qp, *KVp, *Ap, *xr, *cr, *Wqr, *Wkv, *Wor, *bkv;
    cudaGetSymbolAddress((void**)&Qp,  g_Q);
    cudaGetSymbolAddress((void**)&KVp, g_KV);
    cudaGetSymbolAddress((void**)&Ap,  g_A);
    cudaGetSymbolAddress((void**)&xr,  g_xr);
    cudaGetSymbolAddress((void**)&cr,  g_cr);
    cudaGetSymbolAddress((void**)&Wqr, g_Wq);
    cudaGetSymbolAddress((void**)&Wkv, g_Wkv);
    cudaGetSymbolAddress((void**)&Wor, g_Wo);
    cudaGetSymbolAddress((void**)&bkv, g_bkv);

    cudaFuncSetAttribute(attn_kernel,
                         cudaFuncAttributeMaxDynamicSharedMemorySize, ATTN_SMEM);
    cudaFuncSetAttribute(gemm_tf32,
                         cudaFuncAttributeMaxDynamicSharedMemorySize, GEMM_SMEM);

    // ---- pre-pass: round everything to tf32(rna) once ----
    round_copy<<<1024, 256>>>(x,   xr,  LQ_ * DIM_ / 4);
    round_copy<<<512,  256>>>(ctx, cr,  SK_ * CTX_ / 4);
    round_copy<<<1024, 256>>>(Wq,  Wqr, DIM_ * DIM_ / 4);
    round_copy<<<1024, 256>>>(Wo,  Wor, DIM_ * DIM_ / 4);
    // Wk|Wv concatenated along N into [4096][4096]
    round_copy_cols<<<1024, 256>>>(Wk, Wkv,         DIM_ / 4, 2 * DIM_ / 4, CTX_ * DIM_ / 4);
    round_copy_cols<<<1024, 256>>>(Wv, Wkv + DIM_,  DIM_ / 4, 2 * DIM_ / 4, CTX_ * DIM_ / 4);
    cudaMemcpyAsync(bkv,        bk, DIM_ * sizeof(float), cudaMemcpyDeviceToDevice);
    cudaMemcpyAsync(bkv + DIM_, bv, DIM_ * sizeof(float), cudaMemcpyDeviceToDevice);

    // ---- Q = rmsnorm(x @ Wq + bq) ----
    gemm_tf32<<<dim3(DIM_ / BN, LQ_ / BM), 512, GEMM_SMEM>>>(xr, Wqr, bq, Qp, DIM_, DIM_);
    rmsnorm_rows<<<LQ_, 256>>>(Qp, gq, DIM_);

    // ---- [K|V] = ctx @ [Wk|Wv] + [bk|bv], then rmsnorm(K) ----
    gemm_tf32<<<dim3(2 * DIM_ / BN, SK_ / BM), 512, GEMM_SMEM>>>(cr, Wkv, bkv, KVp, 2 * DIM_, CTX_);
    rmsnorm_rows<<<SK_, 256>>>(KVp, gk, 2 * DIM_);

    // ---- attention ----
    attn_kernel<<<dim3(LQ_ / 32, NH_), 256, ATTN_SMEM>>>(Qp, KVp, KVp + DIM_, Ap, 2 * DIM_);

    // ---- out = A @ Wo + bo ----
    gemm_tf32<<<dim3(DIM_ / BN, LQ_ / BM), 512, GEMM_SMEM>>>(Ap, Wor, bo, out, DIM_, DIM_);
}

// round 4
// speedup vs baseline: 1.6993x; 1.1734x over previous
#include <cuda_runtime.h>
#include <cstdint>
#include <cstddef>

// Problem dims (fixed)
#define DIM_  2048
#define CTX_  4096
#define LQ_   8192
#define SK_   512
#define NH_   16
#define HD_   128

// ---------------------------------------------------------------------------
// Scratch (device globals: allocation-free per harness rules)
// ---------------------------------------------------------------------------
__device__ float g_Q  [(size_t)LQ_ * DIM_];          // Q (normed, scaled, tf32-rounded)
__device__ float g_KV [(size_t)SK_ * (2 * DIM_)];    // K | V concat, stride 4096, rounded
__device__ float g_A  [(size_t)LQ_ * DIM_];          // attention out (tf32-rounded)
__device__ float g_xr [(size_t)LQ_ * DIM_];          // x rounded
__device__ float g_cr [(size_t)SK_ * CTX_];          // ctx rounded
__device__ float g_Wq [(size_t)DIM_ * DIM_];         // Wq rounded [K][N]
__device__ float g_Wkv[(size_t)CTX_ * (2 * DIM_)];   // [K=4096][Wk cols | Wv cols]
__device__ float g_Wo [(size_t)DIM_ * DIM_];
__device__ float g_bkv[2 * DIM_];                    // bk | bv

// ---------------------------------------------------------------------------
// helpers
// ---------------------------------------------------------------------------
__device__ __forceinline__ unsigned f2tf(float x) {
    unsigned r;
    asm("cvt.rna.tf32.f32 %0, %1;" : "=r"(r) : "f"(x));
    return r;
}

__device__ __forceinline__ uint32_t smem_u32(const void* p) {
    uint32_t r;
    asm("{ .reg .u64 t; cvta.to.shared.u64 t, %1; cvt.u32.u64 %0, t; }"
        : "=r"(r) : "l"(p));
    return r;
}

__device__ __forceinline__ void cp16(uint32_t s, const void* g) {
    asm volatile("cp.async.cg.shared.global [%0], [%1], 16;" :: "r"(s), "l"(g));
}

__device__ __forceinline__ void mma8(float* c, const unsigned* a, unsigned b0, unsigned b1) {
    asm volatile(
        "mma.sync.aligned.m16n8k8.row.col.f32.tf32.tf32.f32 "
        "{%0,%1,%2,%3},{%4,%5,%6,%7},{%8,%9},{%0,%1,%2,%3};"
        : "+f"(c[0]), "+f"(c[1]), "+f"(c[2]), "+f"(c[3])
        : "r"(a[0]), "r"(a[1]), "r"(a[2]), "r"(a[3]), "r"(b0), "r"(b1));
}

#define CP_COMMIT() asm volatile("cp.async.commit_group;" ::: "memory")

// ---------------------------------------------------------------------------
// Pre-pass: round fp32 -> tf32(rna)
// ---------------------------------------------------------------------------
__global__ void __launch_bounds__(256)
round_copy(const float* __restrict__ in, float* __restrict__ out, int n4)
{
    int i = blockIdx.x * 256 + threadIdx.x;
    int stride = gridDim.x * 256;
    for (; i < n4; i += stride) {
        float4 v = reinterpret_cast<const float4*>(in)[i];
        v.x = __uint_as_float(f2tf(v.x));
        v.y = __uint_as_float(f2tf(v.y));
        v.z = __uint_as_float(f2tf(v.z));
        v.w = __uint_as_float(f2tf(v.w));
        reinterpret_cast<float4*>(out)[i] = v;
    }
}

__global__ void __launch_bounds__(256)
round_copy_cols(const float* __restrict__ in, float* __restrict__ out,
                int cols4, int ostride4, int n4)
{
    int i = blockIdx.x * 256 + threadIdx.x;
    int stride = gridDim.x * 256;
    for (; i < n4; i += stride) {
        int r  = i / cols4;
        int c4 = i - r * cols4;
        float4 v = reinterpret_cast<const float4*>(in)[i];
        v.x = __uint_as_float(f2tf(v.x));
        v.y = __uint_as_float(f2tf(v.y));
        v.z = __uint_as_float(f2tf(v.z));
        v.w = __uint_as_float(f2tf(v.w));
        reinterpret_cast<float4*>(out)[(size_t)r * ostride4 + c4] = v;
    }
}

// ---------------------------------------------------------------------------
// TF32 mma.sync GEMM: C[M,Ntot] = A[M,K] @ B[K,Ntot] + bias
// 8 warps (256 thr), warp tile WM x WN, CTA tile BM x BN, BK=32, 4 stages.
// A smem [BM][36] words, B smem [32][BN+8] words — conflict-free frag reads.
// ---------------------------------------------------------------------------
template<int BM_, int BN_, int WM_, int WN_>
__global__ void __launch_bounds__(256, 1)
gemm_tf32(const float* __restrict__ A, const float* __restrict__ B,
          const float* __restrict__ bias, float* __restrict__ C,
          int Ntot, int K)
{
    constexpr int ASTR   = 36;
    constexpr int BSTR   = BN_ + 8;
    constexpr int ABYTES = BM_ * ASTR * 4;
    constexpr int STG    = ABYTES + 32 * BSTR * 4;
    constexpr int NCP    = (BM_ * 8 + 8 * BN_) / 256;
    constexpr int NCPA   = BM_ * 8 / 256;
    constexpr int MT     = WM_ / 16;
    constexpr int NT     = WN_ / 8;
    constexpr int NWN    = BN_ / WN_;
    constexpr int BF4    = BN_ / 4;

    extern __shared__ char dsm[];
    const uint32_t sbase = smem_u32(dsm);

    const int tid  = threadIdx.x;
    const int wid  = tid >> 5;
    const int lane = tid & 31;
    const int g    = lane >> 2;
    const int c    = lane & 3;
    const int wm   = (wid / NWN) * WM_;
    const int wn   = (wid % NWN) * WN_;
    const int m0   = blockIdx.y * BM_;
    const int n0   = blockIdx.x * BN_;

    uint32_t off[NCP];
    const float* gp[NCP];
#pragma unroll
    for (int i = 0; i < NCPA; i++) {
        int v = tid + i * 256;
        int row = v >> 3, kp = v & 7;
        off[i] = (uint32_t)(row * (ASTR * 4) + kp * 16);
        gp[i]  = A + (size_t)(m0 + row) * K + kp * 4;
    }
#pragma unroll
    for (int i = NCPA; i < NCP; i++) {
        int bv = tid + i * 256 - BM_ * 8;
        int row = bv / BF4, np = bv % BF4;
        off[i] = (uint32_t)(ABYTES + row * (BSTR * 4) + np * 16);
        gp[i]  = B + (size_t)row * Ntot + n0 + np * 4;
    }

    auto load_stage = [&](int s) {
        const uint32_t sb = sbase + (uint32_t)(s & 3) * STG;
        const size_t ka = (size_t)s * 32;
#pragma unroll
        for (int i = 0; i < NCPA; i++) cp16(sb + off[i], gp[i] + ka);
#pragma unroll
        for (int i = NCPA; i < NCP; i++) cp16(sb + off[i], gp[i] + ka * Ntot);
    };

    float acc[MT][NT][4];
#pragma unroll
    for (int mt = 0; mt < MT; mt++)
#pragma unroll
        for (int nt = 0; nt < NT; nt++)
#pragma unroll
            for (int t = 0; t < 4; t++) acc[mt][nt][t] = 0.f;

    const int KT = K / 32;

#pragma unroll
    for (int s = 0; s < 3; s++) { load_stage(s); CP_COMMIT(); }

    for (int kt = 0; kt < KT; kt++) {
        if (kt + 3 < KT) load_stage(kt + 3);
        CP_COMMIT();
        asm volatile("cp.async.wait_group 3;" ::: "memory");
        __syncthreads();

        const unsigned* As = reinterpret_cast<const unsigned*>(
            dsm + (size_t)(kt & 3) * STG);
        const unsigned* Bs = reinterpret_cast<const unsigned*>(
            dsm + (size_t)(kt & 3) * STG + ABYTES);

#pragma unroll
        for (int k8 = 0; k8 < 32; k8 += 8) {
            unsigned a[MT][4];
#pragma unroll
            for (int mt = 0; mt < MT; mt++) {
                const int r = wm + mt * 16 + g;
                a[mt][0] = As[r * ASTR + k8 + c];
                a[mt][1] = As[(r + 8) * ASTR + k8 + c];
                a[mt][2] = As[r * ASTR + k8 + c + 4];
                a[mt][3] = As[(r + 8) * ASTR + k8 + c + 4];
            }
            unsigned b[NT][2];
#pragma unroll
            for (int nt = 0; nt < NT; nt++) {
                const int n = wn + nt * 8 + g;
                b[nt][0] = Bs[(k8 + c) * BSTR + n];
                b[nt][1] = Bs[(k8 + c + 4) * BSTR + n];
            }
#pragma unroll
            for (int mt = 0; mt < MT; mt++)
#pragma unroll
                for (int nt = 0; nt < NT; nt++)
                    mma8(acc[mt][nt], a[mt], b[nt][0], b[nt][1]);
        }
        __syncthreads();
    }

    // epilogue
#pragma unroll
    for (int mt = 0; mt < MT; mt++) {
        const int r0 = m0 + wm + mt * 16 + g;
#pragma unroll
        for (int nt = 0; nt < NT; nt++) {
            const int col = n0 + wn + nt * 8 + 2 * c;
            const float2 bb = *reinterpret_cast<const float2*>(bias + col);
            float2 o0, o1;
            o0.x = acc[mt][nt][0] + bb.x;  o0.y = acc[mt][nt][1] + bb.y;
            o1.x = acc[mt][nt][2] + bb.x;  o1.y = acc[mt][nt][3] + bb.y;
            *reinterpret_cast<float2*>(C + (size_t)r0 * Ntot + col)       = o0;
            *reinterpret_cast<float2*>(C + (size_t)(r0 + 8) * Ntot + col) = o1;
        }
    }
}

#define GEMM1_SMEM ((128 * 36 * 4 + 32 * 264 * 4) * 4)   // 208896
#define GEMM2_SMEM ((128 * 36 * 4 + 32 * 136 * 4) * 4)   // 143360

// ---------------------------------------------------------------------------
// RMSNorm Q: normalize, * g, * 1/sqrt(HD), tf32-round (in place). Row = 2048.
// ---------------------------------------------------------------------------
__global__ void __launch_bounds__(256)
rms_q(float* __restrict__ X, const float* __restrict__ gw)
{
    float* x = X + (size_t)blockIdx.x * DIM_;

    float ss = 0.f;
    for (int i = threadIdx.x; i < DIM_ / 4; i += 256) {
        float4 v = reinterpret_cast<float4*>(x)[i];
        ss += v.x * v.x + v.y * v.y + v.z * v.z + v.w * v.w;
    }
#pragma unroll
    for (int off = 16; off; off >>= 1) ss += __shfl_xor_sync(0xFFFFFFFFu, ss, off);
    __shared__ float red[8];
    if ((threadIdx.x & 31) == 0) red[threadIdx.x >> 5] = ss;
    __syncthreads();
    float tot = 0.f;
#pragma unroll
    for (int i = 0; i < 8; i++) tot += red[i];

    const float sc = rsqrtf(tot / (float)DIM_ + 1e-6f) * 0.08838834764831845f;

    for (int i = threadIdx.x; i < DIM_ / 4; i += 256) {
        float4 v = reinterpret_cast<float4*>(x)[i];
        float4 w = reinterpret_cast<const float4*>(gw)[i];
        v.x = __uint_as_float(f2tf(v.x * sc * w.x));
        v.y = __uint_as_float(f2tf(v.y * sc * w.y));
        v.z = __uint_as_float(f2tf(v.z * sc * w.z));
        v.w = __uint_as_float(f2tf(v.w * sc * w.w));
        reinterpret_cast<float4*>(x)[i] = v;
    }
}

// ---------------------------------------------------------------------------
// RMSNorm KV: row = 4096 = [K(2048) | V(2048)]. Normalize+g+round K, round V.
// ---------------------------------------------------------------------------
__global__ void __launch_bounds__(256)
rms_kv(float* __restrict__ X, const float* __restrict__ gw)
{
    float* x = X + (size_t)blockIdx.x * (2 * DIM_);

    float ss = 0.f;
    for (int i = threadIdx.x; i < DIM_ / 4; i += 256) {
        float4 v = reinterpret_cast<float4*>(x)[i];
        ss += v.x * v.x + v.y * v.y + v.z * v.z + v.w * v.w;
    }
#pragma unroll
    for (int off = 16; off; off >>= 1) ss += __shfl_xor_sync(0xFFFFFFFFu, ss, off);
    __shared__ float red[8];
    if ((threadIdx.x & 31) == 0) red[threadIdx.x >> 5] = ss;
    __syncthreads();
    float tot = 0.f;
#pragma unroll
    for (int i = 0; i < 8; i++) tot += red[i];

    const float sc = rsqrtf(tot / (float)DIM_ + 1e-6f);

    for (int i = threadIdx.x; i < DIM_ / 4; i += 256) {
        float4 v = reinterpret_cast<float4*>(x)[i];
        float4 w = reinterpret_cast<const float4*>(gw)[i];
        v.x = __uint_as_float(f2tf(v.x * sc * w.x));
        v.y = __uint_as_float(f2tf(v.y * sc * w.y));
        v.z = __uint_as_float(f2tf(v.z * sc * w.z));
        v.w = __uint_as_float(f2tf(v.w * sc * w.w));
        reinterpret_cast<float4*>(x)[i] = v;
    }
    for (int i = DIM_ / 4 + threadIdx.x; i < DIM_ / 2; i += 256) {
        float4 v = reinterpret_cast<float4*>(x)[i];
        v.x = __uint_as_float(f2tf(v.x));
        v.y = __uint_as_float(f2tf(v.y));
        v.z = __uint_as_float(f2tf(v.z));
        v.w = __uint_as_float(f2tf(v.w));
        reinterpret_cast<float4*>(x)[i] = v;
    }
}

// ---------------------------------------------------------------------------
// Attention: per CTA = one head x 32 query rows. Q,K,V pre-rounded tf32.
// cp.async loads, double-buffered K/V tiles, full S=512 scores in smem.
// ---------------------------------------------------------------------------
#define KVW (64 * 132)
#define ATTN_SMEM ((32 * 132 + 2 * KVW + 32 * 516 + 32) * 4)

__global__ void __launch_bounds__(256)
attn_kernel(const float* __restrict__ Q, const float* __restrict__ Kc,
            const float* __restrict__ V, float* __restrict__ O, int kvstride)
{
    extern __shared__ float sm[];
    const uint32_t sbase = smem_u32(sm);
    unsigned* Qs  = reinterpret_cast<unsigned*>(sm);          // [32][132]
    unsigned* KVw = Qs + 32 * 132;                            // 2 x [64][132]
    float*    Sc  = reinterpret_cast<float*>(KVw + 2 * KVW);  // [32][516]
    float*    rsum = Sc + 32 * 516;                           // [32]

    const uint32_t q_base  = sbase;
    const uint32_t kv_base = sbase + 32 * 132 * 4;

    const int tid  = threadIdx.x;
    const int wid  = tid >> 5;
    const int lane = tid & 31;
    const int g    = lane >> 2;
    const int c    = lane & 3;
    const int l0   = blockIdx.x * 32;
    const int h    = blockIdx.y;

    const float* Qp = Q + (size_t)l0 * DIM_ + h * HD_;
    const float* Kp = Kc + h * HD_;
    const float* Vp = V + h * HD_;

    auto load_kv = [&](const float* src, int t) {
        const uint32_t b = kv_base + (uint32_t)(t & 1) * (KVW * 4);
#pragma unroll
        for (int i = 0; i < 8; i++) {
            int v   = tid + i * 256;
            int row = v >> 5;            // 0..63
            int dv  = (v & 31) * 4;
            cp16(b + (uint32_t)(row * 132 + dv) * 4,
                 src + (size_t)(t * 64 + row) * kvstride + dv);
        }
    };

    // prologue: Q tile + K tile 0 in one group
#pragma unroll
    for (int i = 0; i < 4; i++) {
        int v   = tid + i * 256;
        int row = v >> 5;
        int dv  = (v & 31) * 4;
        cp16(q_base + (uint32_t)(row * 132 + dv) * 4, Qp + (size_t)row * DIM_ + dv);
    }
    load_kv(Kp, 0);
    CP_COMMIT();

    // ---- pass 1: scores = Q @ K^T ----
    for (int t = 0; t < 8; t++) {
        if (t < 7) {
            load_kv(Kp, t + 1);
            CP_COMMIT();
            asm volatile("cp.async.wait_group 1;" ::: "memory");
        } else {
            asm volatile("cp.async.wait_group 0;" ::: "memory");
        }
        __syncthreads();
        const unsigned* KB = KVw + (t & 1) * KVW;
        const int s0 = t * 64;

        float acc[2][4];
#pragma unroll
        for (int mt = 0; mt < 2; mt++)
#pragma unroll
            for (int i = 0; i < 4; i++) acc[mt][i] = 0.f;

#pragma unroll
        for (int ks = 0; ks < 16; ks++) {
            const int k8 = ks * 8;
            unsigned a[2][4];
#pragma unroll
            for (int mt = 0; mt < 2; mt++) {
                int r = mt * 16 + g;
                a[mt][0] = Qs[r * 132 + k8 + c];
                a[mt][1] = Qs[(r + 8) * 132 + k8 + c];
                a[mt][2] = Qs[r * 132 + k8 + c + 4];
                a[mt][3] = Qs[(r + 8) * 132 + k8 + c + 4];
            }
            unsigned b0 = KB[(wid * 8 + g) * 132 + k8 + c];
            unsigned b1 = KB[(wid * 8 + g) * 132 + k8 + c + 4];
#pragma unroll
            for (int mt = 0; mt < 2; mt++) mma8(acc[mt], a[mt], b0, b1);
        }
#pragma unroll
        for (int mt = 0; mt < 2; mt++) {
            int r   = mt * 16 + g;
            int col = s0 + wid * 8 + 2 * c;
            Sc[r * 516 + col]           = acc[mt][0];
            Sc[r * 516 + col + 1]       = acc[mt][1];
            Sc[(r + 8) * 516 + col]     = acc[mt][2];
            Sc[(r + 8) * 516 + col + 1] = acc[mt][3];
        }
        __syncthreads();
    }

    // prefetch V tile 0 (overlaps softmax)
    load_kv(Vp, 0);
    CP_COMMIT();

    // ---- softmax: warp wid handles rows 4*wid..4*wid+3 ----
#pragma unroll
    for (int rr = 0; rr < 4; rr++) {
        const int row = wid * 4 + rr;
        float mx = -1e30f;
        for (int j = lane; j < 512; j += 32) mx = fmaxf(mx, Sc[row * 516 + j]);
#pragma unroll
        for (int off = 16; off; off >>= 1)
            mx = fmaxf(mx, __shfl_xor_sync(0xFFFFFFFFu, mx, off));
        float sum = 0.f;
        for (int j = lane; j < 512; j += 32) {
            float e = __expf(Sc[row * 516 + j] - mx);
            sum += e;
            Sc[row * 516 + j] = __uint_as_float(f2tf(e));
        }
#pragma unroll
        for (int off = 16; off; off >>= 1) sum += __shfl_xor_sync(0xFFFFFFFFu, sum, off);
        if (lane == 0) rsum[row] = sum;
    }

    // ---- pass 2: O = P @ V ----
    float o[2][2][4];
#pragma unroll
    for (int mt = 0; mt < 2; mt++)
#pragma unroll
        for (int nt = 0; nt < 2; nt++)
#pragma unroll
            for (int i = 0; i < 4; i++) o[mt][nt][i] = 0.f;

    for (int t = 0; t < 8; t++) {
        if (t < 7) {
            load_kv(Vp, t + 1);
            CP_COMMIT();
            asm volatile("cp.async.wait_group 1;" ::: "memory");
        } else {
            asm volatile("cp.async.wait_group 0;" ::: "memory");
        }
        __syncthreads();
        const unsigned* VB = KVw + (t & 1) * KVW;
        const int s0 = t * 64;

#pragma unroll
        for (int ks = 0; ks < 8; ks++) {
            const int kk = s0 + ks * 8;
            unsigned a[2][4];
#pragma unroll
            for (int mt = 0; mt < 2; mt++) {
                int r = mt * 16 + g;
                a[mt][0] = __float_as_uint(Sc[r * 516 + kk + c]);
                a[mt][1] = __float_as_uint(Sc[(r + 8) * 516 + kk + c]);
                a[mt][2] = __float_as_uint(Sc[r * 516 + kk + c + 4]);
                a[mt][3] = __float_as_uint(Sc[(r + 8) * 516 + kk + c + 4]);
            }
#pragma unroll
            for (int nt = 0; nt < 2; nt++) {
                int n = wid * 16 + nt * 8 + g;
                unsigned b0 = VB[(ks * 8 + c) * 132 + n];
                unsigned b1 = VB[(ks * 8 + c + 4) * 132 + n];
#pragma unroll
                for (int mt = 0; mt < 2; mt++) mma8(o[mt][nt], a[mt], b0, b1);
            }
        }
        __syncthreads();
    }

    // ---- epilogue: normalize + tf32-round (O-proj then truncates exactly) ----
#pragma unroll
    for (int mt = 0; mt < 2; mt++) {
        const float inv0 = 1.f / rsum[mt * 16 + g];
        const float inv1 = 1.f / rsum[mt * 16 + g + 8];
        const int row = l0 + mt * 16 + g;
#pragma unroll
        for (int nt = 0; nt < 2; nt++) {
            int col = h * HD_ + wid * 16 + nt * 8 + 2 * c;
            O[(size_t)row * DIM_ + col]           = __uint_as_float(f2tf(o[mt][nt][0] * inv0));
            O[(size_t)row * DIM_ + col + 1]       = __uint_as_float(f2tf(o[mt][nt][1] * inv0));
            O[(size_t)(row + 8) * DIM_ + col]     = __uint_as_float(f2tf(o[mt][nt][2] * inv1));
            O[(size_t)(row + 8) * DIM_ + col + 1] = __uint_as_float(f2tf(o[mt][nt][3] * inv1));
        }
    }
}

// ---------------------------------------------------------------------------
// kernel_launch
// ---------------------------------------------------------------------------
extern "C" void kernel_launch(void* const* d_in, const int* in_sizes, int n_in,
                              void* d_out, int out_size)
{
    const float* x   = (const float*)d_in[0];
    const float* ctx = (const float*)d_in[1];
    const float* Wq  = (const float*)d_in[2];
    const float* bq  = (const float*)d_in[3];
    const float* Wk  = (const float*)d_in[4];
    const float* bk  = (const float*)d_in[5];
    const float* Wv  = (const float*)d_in[6];
    const float* bv  = (const float*)d_in[7];
    const float* Wo  = (const float*)d_in[8];
    const float* bo  = (const float*)d_in[9];
    const float* gq  = (const float*)d_in[10];
    const float* gk  = (const float*)d_in[11];
    float* out = (float*)d_out;

    float *Qp, *KVp, *Ap, *xr, *cr, *Wqr, *Wkv, *Wor, *bkv;
    cudaGetSymbolAddress((void**)&Qp,  g_Q);
    cudaGetSymbolAddress((void**)&KVp, g_KV);
    cudaGetSymbolAddress((void**)&Ap,  g_A);
    cudaGetSymbolAddress((void**)&xr,  g_xr);
    cudaGetSymbolAddress((void**)&cr,  g_cr);
    cudaGetSymbolAddress((void**)&Wqr, g_Wq);
    cudaGetSymbolAddress((void**)&Wkv, g_Wkv);
    cudaGetSymbolAddress((void**)&Wor, g_Wo);
    cudaGetSymbolAddress((void**)&bkv, g_bkv);

    auto gemm_big   = gemm_tf32<128, 256, 64, 64>;
    auto gemm_small = gemm_tf32<128, 128, 64, 32>;
    cudaFuncSetAttribute(gemm_big,
                         cudaFuncAttributeMaxDynamicSharedMemorySize, GEMM1_SMEM);
    cudaFuncSetAttribute(gemm_small,
                         cudaFuncAttributeMaxDynamicSharedMemorySize, GEMM2_SMEM);
    cudaFuncSetAttribute(attn_kernel,
                         cudaFuncAttributeMaxDynamicSharedMemorySize, ATTN_SMEM);

    // ---- pre-pass: round everything to tf32(rna) once ----
    round_copy<<<1024, 256>>>(x,   xr,  LQ_ * DIM_ / 4);
    round_copy<<<512,  256>>>(ctx, cr,  SK_ * CTX_ / 4);
    round_copy<<<1024, 256>>>(Wq,  Wqr, DIM_ * DIM_ / 4);
    round_copy<<<1024, 256>>>(Wo,  Wor, DIM_ * DIM_ / 4);
    round_copy_cols<<<1024, 256>>>(Wk, Wkv,        DIM_ / 4, 2 * DIM_ / 4, CTX_ * DIM_ / 4);
    round_copy_cols<<<1024, 256>>>(Wv, Wkv + DIM_, DIM_ / 4, 2 * DIM_ / 4, CTX_ * DIM_ / 4);
    cudaMemcpyAsync(bkv,        bk, DIM_ * sizeof(float), cudaMemcpyDeviceToDevice);
    cudaMemcpyAsync(bkv + DIM_, bv, DIM_ * sizeof(float), cudaMemcpyDeviceToDevice);

    // ---- Q = round(rmsnorm(x @ Wq + bq) * scale) ----
    gemm_big<<<dim3(DIM_ / 256, LQ_ / 128), 256, GEMM1_SMEM>>>(xr, Wqr, bq, Qp, DIM_, DIM_);
    rms_q<<<LQ_, 256>>>(Qp, gq);

    // ---- [K|V] = ctx @ [Wk|Wv] + [bk|bv]; round(rmsnorm(K)), round(V) ----
    gemm_small<<<dim3(2 * DIM_ / 128, SK_ / 128), 256, GEMM2_SMEM>>>(cr, Wkv, bkv, KVp, 2 * DIM_, CTX_);
    rms_kv<<<SK_, 256>>>(KVp, gk);

    // ---- attention ----
    attn_kernel<<<dim3(LQ_ / 32, NH_), 256, ATTN_SMEM>>>(Qp, KVp, KVp + DIM_, Ap, 2 * DIM_);

    // ---- out = A @ Wo + bo ----
    gemm_big<<<dim3(DIM_ / 256, LQ_ / 128), 256, GEMM1_SMEM>>>(Ap, Wor, bo, out, DIM_, DIM_);
}